// round 3
// baseline (speedup 1.0000x reference)
#include <cuda_runtime.h>
#include <cstdint>

// CorrelationAlign: out[b, a*63+c, i, j] = corr[b, (a-31+i)*32 + (c-31+j), i, j]
// when 0 <= a-31+i < 32 and 0 <= c-31+j < 32, else 0.
//
// corr : float[16][1024][32][32]  (b, p*32+q, i, j)
// out  : float[16][3969][32][32]  (b, a*63+c, i, j)
//
// Block = (b, i, group-of-7 a's). For each a in the group, p = a-31+i is
// uniform. Load up to 7 slabs (32x32 each) coalesced into padded smem with
// MLP=7, one barrier, then write 7*63 output rows of 128B (shifted gather,
// zero-filled edges).

static constexpr int Hh   = 32;   // h == w == 32
static constexpr int HWo  = 63;   // 2*h-1
static constexpr int G    = 7;    // a-values per block (63 = 9*7)
static constexpr int NG   = 9;
static constexpr int THREADS = 256;

__global__ __launch_bounds__(THREADS, 4)
void corr_align_kernel(const float* __restrict__ corr, float* __restrict__ out)
{
    const int bx = blockIdx.x;
    const int i  = bx & 31;                 // 0..31
    const int g  = (bx >> 5) % NG;          // 0..8
    const int b  = bx / (NG * Hh);          // 0..15

    const int a0 = g * G;
    const int p0 = a0 - (Hh - 1) + i;       // p for a_local = 0

    __shared__ float tile[G][Hh * 33];      // pad 32->33: conflict-free shifted reads

    const int t  = threadIdx.x;
    const int q  = t >> 3;                  // 0..31
    const int j4 = (t & 7) << 2;            // 0,4,...,28

    const float* src0 = corr + ((size_t)b << 20) + (size_t)i * 32 + j4;

    // Load phase: up to 7 independent slab loads per thread (high MLP).
    #pragma unroll
    for (int al = 0; al < G; ++al) {
        const int p = p0 + al;
        if (p >= 0 && p < Hh) {
            const float4 v = __ldcs((const float4*)(src0 + (size_t)(p * Hh + q) * 1024));
            float* d = &tile[al][q * 33 + j4];
            d[0] = v.x; d[1] = v.y; d[2] = v.z; d[3] = v.w;
        }
    }
    __syncthreads();

    // Store phase: for each a in group, 63 rows x 32 floats = 504 float4s.
    float* ob = out + (size_t)b * (HWo * HWo) * 1024
                    + (size_t)a0 * HWo * 1024
                    + (size_t)i * 32;

    #pragma unroll 1
    for (int al = 0; al < G; ++al) {
        const int  p  = p0 + al;
        const bool pv = (p >= 0) && (p < Hh);
        float* oba = ob + (size_t)al * HWo * 1024;

        #pragma unroll
        for (int iter = 0; iter < 2; ++iter) {
            const int idx = t + iter * THREADS;
            if (idx < HWo * 8) {
                const int c   = idx >> 3;        // 0..62
                const int jj4 = (idx & 7) << 2;  // 0,4,...,28
                const int qb  = c - (Hh - 1) + jj4;
                float4 v;
                v.x = (pv && (qb + 0) >= 0 && (qb + 0) < Hh) ? tile[al][(qb + 0) * 33 + jj4 + 0] : 0.0f;
                v.y = (pv && (qb + 1) >= 0 && (qb + 1) < Hh) ? tile[al][(qb + 1) * 33 + jj4 + 1] : 0.0f;
                v.z = (pv && (qb + 2) >= 0 && (qb + 2) < Hh) ? tile[al][(qb + 2) * 33 + jj4 + 2] : 0.0f;
                v.w = (pv && (qb + 3) >= 0 && (qb + 3) < Hh) ? tile[al][(qb + 3) * 33 + jj4 + 3] : 0.0f;
                __stcs((float4*)(oba + (size_t)c * 1024 + jj4), v);
            }
        }
    }
}

extern "C" void kernel_launch(void* const* d_in, const int* in_sizes, int n_in,
                              void* d_out, int out_size)
{
    const float* corr = (const float*)d_in[0];
    float*       out  = (float*)d_out;
    (void)in_sizes; (void)n_in; (void)out_size;

    const int grid = 16 * NG * Hh;          // 16 * 9 * 32 = 4608
    corr_align_kernel<<<grid, THREADS>>>(corr, out);
}